// round 5
// baseline (speedup 1.0000x reference)
#include <cuda_runtime.h>
#include <cstdint>

#define N_NODES 50000
#define N_EDGES 1600000
#define F 48
#define NREL 8

// transform tiling
#define NT 64
#define NTP (NT + 4)
#define TPB1 192

// scan config
#define SCB 1024
#define SB ((N_NODES + SCB - 1) / SCB)   // 49 blocks

// agg config
#define GPD 16                            // dst nodes per block (16*12 = 192 thr)
#define TPBA 192

typedef unsigned long long u64;

// ------------------------- static device scratch ---------------------------
__device__ float g_h2[(size_t)N_NODES * NREL * F];   // 76.8 MB
__device__ int   g_counts[N_NODES];
__device__ int   g_offsets[N_NODES + 1];
__device__ int   g_cursors[N_NODES];
__device__ u64   g_recs[N_EDGES];                    // {norm:f32 hi, srel:u32 lo}
__device__ int   g_blocksums[SB];

// ---------------------------------------------------------------------------
// Kernel 1: h2[n,r,:] = relu(x[n] @ W1[r] + b1) @ W2[r]
// ---------------------------------------------------------------------------
__global__ __launch_bounds__(TPB1) void transform_kernel(
    const float* __restrict__ x, const float* __restrict__ W1,
    const float* __restrict__ W2, const float* __restrict__ b1)
{
    __shared__ __align__(16) float sW1[F * F];
    __shared__ __align__(16) float sW2[F * F];
    __shared__ __align__(16) float sT[F][NTP];   // xT, then h1T

    const int r   = blockIdx.y;
    const int n0  = blockIdx.x * NT;
    const int tid = threadIdx.x;
    const int cg  = tid % 12;
    const int ng  = tid / 12;

    for (int i = tid; i < F * F; i += TPB1) {
        sW1[i] = W1[(size_t)r * F * F + i];
        sW2[i] = W2[(size_t)r * F * F + i];
    }
    for (int idx = tid; idx < NT * F; idx += TPB1) {
        int n = idx / F, i = idx % F;
        int gn = n0 + n;
        sT[i][n] = (gn < N_NODES) ? x[(size_t)gn * F + i] : 0.f;
    }
    __syncthreads();

    float acc[4][4];

    #pragma unroll
    for (int u = 0; u < 4; u++)
        #pragma unroll
        for (int c = 0; c < 4; c++) acc[u][c] = 0.f;

    #pragma unroll 8
    for (int i = 0; i < F; i++) {
        float4 xv = *reinterpret_cast<const float4*>(&sT[i][ng * 4]);
        float4 wv = *reinterpret_cast<const float4*>(&sW1[i * F + cg * 4]);
        float xa[4] = {xv.x, xv.y, xv.z, xv.w};
        float wa[4] = {wv.x, wv.y, wv.z, wv.w};
        #pragma unroll
        for (int u = 0; u < 4; u++)
            #pragma unroll
            for (int c = 0; c < 4; c++)
                acc[u][c] += xa[u] * wa[c];
    }
    __syncthreads();   // done reading sT

    {
        float4 bv = *reinterpret_cast<const float4*>(&b1[cg * 4]);
        float ba[4] = {bv.x, bv.y, bv.z, bv.w};
        #pragma unroll
        for (int c = 0; c < 4; c++) {
            float4 hv;
            hv.x = fmaxf(acc[0][c] + ba[c], 0.f);
            hv.y = fmaxf(acc[1][c] + ba[c], 0.f);
            hv.z = fmaxf(acc[2][c] + ba[c], 0.f);
            hv.w = fmaxf(acc[3][c] + ba[c], 0.f);
            *reinterpret_cast<float4*>(&sT[cg * 4 + c][ng * 4]) = hv;
        }
    }
    __syncthreads();

    #pragma unroll
    for (int u = 0; u < 4; u++)
        #pragma unroll
        for (int c = 0; c < 4; c++) acc[u][c] = 0.f;

    #pragma unroll 8
    for (int j = 0; j < F; j++) {
        float4 hv = *reinterpret_cast<const float4*>(&sT[j][ng * 4]);
        float4 wv = *reinterpret_cast<const float4*>(&sW2[j * F + cg * 4]);
        float ha[4] = {hv.x, hv.y, hv.z, hv.w};
        float wa[4] = {wv.x, wv.y, wv.z, wv.w};
        #pragma unroll
        for (int u = 0; u < 4; u++)
            #pragma unroll
            for (int c = 0; c < 4; c++)
                acc[u][c] += ha[u] * wa[c];
    }

    #pragma unroll
    for (int u = 0; u < 4; u++) {
        int gn = n0 + ng * 4 + u;
        if (gn < N_NODES) {
            *reinterpret_cast<float4*>(&g_h2[((size_t)gn * NREL + r) * F + cg * 4]) =
                make_float4(acc[u][0], acc[u][1], acc[u][2], acc[u][3]);
        }
    }
}

// ---------------------------------------------------------------------------
// CSR build: histogram -> scan -> scatter packed records
// ---------------------------------------------------------------------------
__global__ void hist_kernel(const int* __restrict__ dst)
{
    int e = blockIdx.x * blockDim.x + threadIdx.x;
    if (e < N_EDGES) atomicAdd(&g_counts[dst[e]], 1);
}

__global__ __launch_bounds__(SCB) void scan1_kernel()
{
    __shared__ int s[SCB];
    int tid = threadIdx.x;
    int i = blockIdx.x * SCB + tid;
    int v = (i < N_NODES) ? g_counts[i] : 0;
    s[tid] = v;
    __syncthreads();
    #pragma unroll
    for (int off = 1; off < SCB; off <<= 1) {
        int t = (tid >= off) ? s[tid - off] : 0;
        __syncthreads();
        s[tid] += t;
        __syncthreads();
    }
    if (i < N_NODES) g_offsets[i] = s[tid] - v;     // local exclusive
    if (tid == SCB - 1) g_blocksums[blockIdx.x] = s[tid];
}

__global__ void scan2_kernel()
{
    if (threadIdx.x == 0) {
        int run = 0;
        #pragma unroll
        for (int b = 0; b < SB; b++) {
            int t = g_blocksums[b];
            g_blocksums[b] = run;
            run += t;
        }
        g_offsets[N_NODES] = run;   // == N_EDGES
    }
}

__global__ __launch_bounds__(SCB) void scan3_kernel()
{
    int i = blockIdx.x * SCB + threadIdx.x;
    if (i < N_NODES) {
        int o = g_offsets[i] + g_blocksums[blockIdx.x];
        g_offsets[i] = o;
        g_cursors[i] = o;
    }
}

__global__ void scatter_kernel(
    const int* __restrict__ src, const int* __restrict__ dst,
    const int* __restrict__ rel, const float* __restrict__ norm)
{
    int e = blockIdx.x * blockDim.x + threadIdx.x;
    if (e >= N_EDGES) return;
    int d = dst[e];
    int pos = atomicAdd(&g_cursors[d], 1);
    uint32_t srel = (uint32_t)src[e] * NREL + (uint32_t)rel[e];
    uint32_t wb = __float_as_uint(norm[e]);
    g_recs[pos] = ((u64)wb << 32) | (u64)srel;
}

// ---------------------------------------------------------------------------
// Aggregation: 12 lanes per dst node accumulate all incoming messages in
// registers (2-edge unroll, dual accumulators -> ~4 loads in flight/thread),
// then fused bias2+relu store. No atomics, no output memset.
// ---------------------------------------------------------------------------
__global__ __launch_bounds__(TPBA) void agg_kernel(
    const float* __restrict__ b2, float* __restrict__ out)
{
    const int tid = threadIdx.x;
    const int g = blockIdx.x * GPD + tid / 12;
    const int k = tid % 12;
    if (g >= N_NODES) return;

    const int start = g_offsets[g];
    const int end   = g_offsets[g + 1];

    float4 acc0 = make_float4(0.f, 0.f, 0.f, 0.f);
    float4 acc1 = make_float4(0.f, 0.f, 0.f, 0.f);

    int e = start;
    for (; e + 1 < end; e += 2) {
        u64 r0 = g_recs[e];
        u64 r1 = g_recs[e + 1];
        float w0 = __uint_as_float((uint32_t)(r0 >> 32));
        float w1 = __uint_as_float((uint32_t)(r1 >> 32));
        float4 v0 = *reinterpret_cast<const float4*>(
            &g_h2[(size_t)(uint32_t)r0 * F + k * 4]);
        float4 v1 = *reinterpret_cast<const float4*>(
            &g_h2[(size_t)(uint32_t)r1 * F + k * 4]);
        acc0.x += v0.x * w0; acc0.y += v0.y * w0;
        acc0.z += v0.z * w0; acc0.w += v0.w * w0;
        acc1.x += v1.x * w1; acc1.y += v1.y * w1;
        acc1.z += v1.z * w1; acc1.w += v1.w * w1;
    }
    if (e < end) {
        u64 r0 = g_recs[e];
        float w0 = __uint_as_float((uint32_t)(r0 >> 32));
        float4 v0 = *reinterpret_cast<const float4*>(
            &g_h2[(size_t)(uint32_t)r0 * F + k * 4]);
        acc0.x += v0.x * w0; acc0.y += v0.y * w0;
        acc0.z += v0.z * w0; acc0.w += v0.w * w0;
    }

    float4 bv = reinterpret_cast<const float4*>(b2)[k];
    float4 o;
    o.x = fmaxf(acc0.x + acc1.x + bv.x, 0.f);
    o.y = fmaxf(acc0.y + acc1.y + bv.y, 0.f);
    o.z = fmaxf(acc0.z + acc1.z + bv.z, 0.f);
    o.w = fmaxf(acc0.w + acc1.w + bv.w, 0.f);
    *reinterpret_cast<float4*>(&out[(size_t)g * F + k * 4]) = o;
}

// ---------------------------------------------------------------------------
extern "C" void kernel_launch(void* const* d_in, const int* in_sizes, int n_in,
                              void* d_out, int out_size)
{
    const float* x    = (const float*)d_in[0];
    const float* norm = (const float*)d_in[1];
    const float* W1   = (const float*)d_in[2];
    const float* W2   = (const float*)d_in[3];
    const float* b1   = (const float*)d_in[4];
    const float* b2   = (const float*)d_in[5];
    const int*   src  = (const int*)d_in[6];
    const int*   dst  = (const int*)d_in[7];
    const int*   rel  = (const int*)d_in[8];
    float* out = (float*)d_out;

    // one-time side stream + fork/join events (created on the first,
    // uncaptured, correctness call; reused by every capture/replay)
    static cudaStream_t s2 = nullptr;
    static cudaEvent_t evFork = nullptr, evJoin = nullptr;
    static bool streams_ok = false;
    if (!evJoin) {
        streams_ok =
            cudaStreamCreateWithFlags(&s2, cudaStreamNonBlocking) == cudaSuccess &&
            cudaEventCreateWithFlags(&evFork, cudaEventDisableTiming) == cudaSuccess &&
            cudaEventCreateWithFlags(&evJoin, cudaEventDisableTiming) == cudaSuccess;
    }

    void* counts_ptr = nullptr;
    cudaGetSymbolAddress(&counts_ptr, g_counts);

    cudaStream_t sb = streams_ok ? s2 : (cudaStream_t)0;   // CSR-build stream

    if (streams_ok) {
        cudaEventRecord(evFork, 0);
        cudaStreamWaitEvent(sb, evFork, 0);
    }

    // ---- CSR build (side stream; independent of transform) ----
    cudaMemsetAsync(counts_ptr, 0, N_NODES * sizeof(int), sb);
    hist_kernel<<<(N_EDGES + 255) / 256, 256, 0, sb>>>(dst);
    scan1_kernel<<<SB, SCB, 0, sb>>>();
    scan2_kernel<<<1, 32, 0, sb>>>();
    scan3_kernel<<<SB, SCB, 0, sb>>>();
    scatter_kernel<<<(N_EDGES + 255) / 256, 256, 0, sb>>>(src, dst, rel, norm);

    // ---- per-(node,rel) transform (main stream, runs concurrently) ----
    dim3 g1((N_NODES + NT - 1) / NT, NREL);
    transform_kernel<<<g1, TPB1>>>(x, W1, W2, b1);

    if (streams_ok) {
        cudaEventRecord(evJoin, sb);
        cudaStreamWaitEvent((cudaStream_t)0, evJoin, 0);
    }

    // ---- gather + reduce + bias + relu (needs both) ----
    agg_kernel<<<(N_NODES + GPD - 1) / GPD, TPBA>>>(b2, out);
}

// round 6
// speedup vs baseline: 1.1314x; 1.1314x over previous
#include <cuda_runtime.h>
#include <cuda_fp16.h>
#include <cstdint>

#define N_NODES 50000
#define N_EDGES 1600000
#define F 48
#define NREL 8

// transform tiling
#define NT 64
#define NTP (NT + 4)
#define TPB1 192

// scan config
#define SCB 1024
#define SB ((N_NODES + SCB - 1) / SCB)   // 49 blocks

// agg config
#define GPD 16                            // dst nodes per block (16*12 = 192 thr)
#define TPBA 192

typedef unsigned long long u64;

// ------------------------- static device scratch ---------------------------
// h2 stored as fp16: 50000*8*48*2B = 38.4 MB -> L2-resident
__device__ __align__(16) __half g_h2h[(size_t)N_NODES * NREL * F];
__device__ int   g_counts[N_NODES];
__device__ int   g_offsets[N_NODES + 1];
__device__ int   g_cursors[N_NODES];
__device__ u64   g_recs[N_EDGES];                    // {norm:f32 hi, srel:u32 lo}
__device__ int   g_blocksums[SB];

// ---------------------------------------------------------------------------
// Kernel 1: h2[n,r,:] = relu(x[n] @ W1[r] + b1) @ W2[r], stored fp16
// ---------------------------------------------------------------------------
__global__ __launch_bounds__(TPB1) void transform_kernel(
    const float* __restrict__ x, const float* __restrict__ W1,
    const float* __restrict__ W2, const float* __restrict__ b1)
{
    __shared__ __align__(16) float sW1[F * F];
    __shared__ __align__(16) float sW2[F * F];
    __shared__ __align__(16) float sT[F][NTP];   // xT, then h1T

    const int r   = blockIdx.y;
    const int n0  = blockIdx.x * NT;
    const int tid = threadIdx.x;
    const int cg  = tid % 12;
    const int ng  = tid / 12;

    for (int i = tid; i < F * F; i += TPB1) {
        sW1[i] = W1[(size_t)r * F * F + i];
        sW2[i] = W2[(size_t)r * F * F + i];
    }
    for (int idx = tid; idx < NT * F; idx += TPB1) {
        int n = idx / F, i = idx % F;
        int gn = n0 + n;
        sT[i][n] = (gn < N_NODES) ? x[(size_t)gn * F + i] : 0.f;
    }
    __syncthreads();

    float acc[4][4];

    #pragma unroll
    for (int u = 0; u < 4; u++)
        #pragma unroll
        for (int c = 0; c < 4; c++) acc[u][c] = 0.f;

    #pragma unroll 8
    for (int i = 0; i < F; i++) {
        float4 xv = *reinterpret_cast<const float4*>(&sT[i][ng * 4]);
        float4 wv = *reinterpret_cast<const float4*>(&sW1[i * F + cg * 4]);
        float xa[4] = {xv.x, xv.y, xv.z, xv.w};
        float wa[4] = {wv.x, wv.y, wv.z, wv.w};
        #pragma unroll
        for (int u = 0; u < 4; u++)
            #pragma unroll
            for (int c = 0; c < 4; c++)
                acc[u][c] += xa[u] * wa[c];
    }
    __syncthreads();   // done reading sT

    {
        float4 bv = *reinterpret_cast<const float4*>(&b1[cg * 4]);
        float ba[4] = {bv.x, bv.y, bv.z, bv.w};
        #pragma unroll
        for (int c = 0; c < 4; c++) {
            float4 hv;
            hv.x = fmaxf(acc[0][c] + ba[c], 0.f);
            hv.y = fmaxf(acc[1][c] + ba[c], 0.f);
            hv.z = fmaxf(acc[2][c] + ba[c], 0.f);
            hv.w = fmaxf(acc[3][c] + ba[c], 0.f);
            *reinterpret_cast<float4*>(&sT[cg * 4 + c][ng * 4]) = hv;
        }
    }
    __syncthreads();

    #pragma unroll
    for (int u = 0; u < 4; u++)
        #pragma unroll
        for (int c = 0; c < 4; c++) acc[u][c] = 0.f;

    #pragma unroll 8
    for (int j = 0; j < F; j++) {
        float4 hv = *reinterpret_cast<const float4*>(&sT[j][ng * 4]);
        float4 wv = *reinterpret_cast<const float4*>(&sW2[j * F + cg * 4]);
        float ha[4] = {hv.x, hv.y, hv.z, hv.w};
        float wa[4] = {wv.x, wv.y, wv.z, wv.w};
        #pragma unroll
        for (int u = 0; u < 4; u++)
            #pragma unroll
            for (int c = 0; c < 4; c++)
                acc[u][c] += ha[u] * wa[c];
    }

    #pragma unroll
    for (int u = 0; u < 4; u++) {
        int gn = n0 + ng * 4 + u;
        if (gn < N_NODES) {
            __half2 ha = __floats2half2_rn(acc[u][0], acc[u][1]);
            __half2 hb = __floats2half2_rn(acc[u][2], acc[u][3]);
            uint2 p = make_uint2(*reinterpret_cast<uint32_t*>(&ha),
                                 *reinterpret_cast<uint32_t*>(&hb));
            *reinterpret_cast<uint2*>(
                &g_h2h[((size_t)gn * NREL + r) * F + cg * 4]) = p;
        }
    }
}

// ---------------------------------------------------------------------------
// CSR build: histogram -> scan -> scatter packed records
// ---------------------------------------------------------------------------
__global__ void hist_kernel(const int* __restrict__ dst)
{
    int e = blockIdx.x * blockDim.x + threadIdx.x;
    if (e < N_EDGES) atomicAdd(&g_counts[dst[e]], 1);
}

__global__ __launch_bounds__(SCB) void scan1_kernel()
{
    __shared__ int s[SCB];
    int tid = threadIdx.x;
    int i = blockIdx.x * SCB + tid;
    int v = (i < N_NODES) ? g_counts[i] : 0;
    s[tid] = v;
    __syncthreads();
    #pragma unroll
    for (int off = 1; off < SCB; off <<= 1) {
        int t = (tid >= off) ? s[tid - off] : 0;
        __syncthreads();
        s[tid] += t;
        __syncthreads();
    }
    if (i < N_NODES) g_offsets[i] = s[tid] - v;     // local exclusive
    if (tid == SCB - 1) g_blocksums[blockIdx.x] = s[tid];
}

__global__ void scan2_kernel()
{
    if (threadIdx.x == 0) {
        int run = 0;
        #pragma unroll
        for (int b = 0; b < SB; b++) {
            int t = g_blocksums[b];
            g_blocksums[b] = run;
            run += t;
        }
        g_offsets[N_NODES] = run;   // == N_EDGES
    }
}

__global__ __launch_bounds__(SCB) void scan3_kernel()
{
    int i = blockIdx.x * SCB + threadIdx.x;
    if (i < N_NODES) {
        int o = g_offsets[i] + g_blocksums[blockIdx.x];
        g_offsets[i] = o;
        g_cursors[i] = o;
    }
}

__global__ void scatter_kernel(
    const int* __restrict__ src, const int* __restrict__ dst,
    const int* __restrict__ rel, const float* __restrict__ norm)
{
    int e = blockIdx.x * blockDim.x + threadIdx.x;
    if (e >= N_EDGES) return;
    int d = dst[e];
    int pos = atomicAdd(&g_cursors[d], 1);
    uint32_t srel = (uint32_t)src[e] * NREL + (uint32_t)rel[e];
    uint32_t wb = __float_as_uint(norm[e]);
    g_recs[pos] = ((u64)wb << 32) | (u64)srel;
}

// ---------------------------------------------------------------------------
// Aggregation: 12 lanes per dst node; fp16 gather (8B per lane per edge),
// 4-edge unroll with 4 independent accumulators (~8 loads in flight/thread),
// fused bias2+relu fp32 store. No atomics, no output memset.
// ---------------------------------------------------------------------------
__device__ __forceinline__ void acc_edge(float4& a, u64 rec, int k)
{
    float w = __uint_as_float((uint32_t)(rec >> 32));
    uint2 p = *reinterpret_cast<const uint2*>(
        &g_h2h[(size_t)(uint32_t)rec * F + k * 4]);
    __half2 ha = *reinterpret_cast<__half2*>(&p.x);
    __half2 hb = *reinterpret_cast<__half2*>(&p.y);
    float2 fa = __half22float2(ha);
    float2 fb = __half22float2(hb);
    a.x += fa.x * w; a.y += fa.y * w;
    a.z += fb.x * w; a.w += fb.y * w;
}

__global__ __launch_bounds__(TPBA) void agg_kernel(
    const float* __restrict__ b2, float* __restrict__ out)
{
    const int tid = threadIdx.x;
    const int g = blockIdx.x * GPD + tid / 12;
    const int k = tid % 12;
    if (g >= N_NODES) return;

    const int start = g_offsets[g];
    const int end   = g_offsets[g + 1];

    float4 a0 = make_float4(0.f, 0.f, 0.f, 0.f);
    float4 a1 = make_float4(0.f, 0.f, 0.f, 0.f);
    float4 a2 = make_float4(0.f, 0.f, 0.f, 0.f);
    float4 a3 = make_float4(0.f, 0.f, 0.f, 0.f);

    int e = start;
    for (; e + 3 < end; e += 4) {
        u64 r0 = g_recs[e];
        u64 r1 = g_recs[e + 1];
        u64 r2 = g_recs[e + 2];
        u64 r3 = g_recs[e + 3];
        acc_edge(a0, r0, k);
        acc_edge(a1, r1, k);
        acc_edge(a2, r2, k);
        acc_edge(a3, r3, k);
    }
    for (; e < end; e++) acc_edge(a0, g_recs[e], k);

    float4 bv = reinterpret_cast<const float4*>(b2)[k];
    float4 o;
    o.x = fmaxf(a0.x + a1.x + a2.x + a3.x + bv.x, 0.f);
    o.y = fmaxf(a0.y + a1.y + a2.y + a3.y + bv.y, 0.f);
    o.z = fmaxf(a0.z + a1.z + a2.z + a3.z + bv.z, 0.f);
    o.w = fmaxf(a0.w + a1.w + a2.w + a3.w + bv.w, 0.f);
    *reinterpret_cast<float4*>(&out[(size_t)g * F + k * 4]) = o;
}

// ---------------------------------------------------------------------------
extern "C" void kernel_launch(void* const* d_in, const int* in_sizes, int n_in,
                              void* d_out, int out_size)
{
    const float* x    = (const float*)d_in[0];
    const float* norm = (const float*)d_in[1];
    const float* W1   = (const float*)d_in[2];
    const float* W2   = (const float*)d_in[3];
    const float* b1   = (const float*)d_in[4];
    const float* b2   = (const float*)d_in[5];
    const int*   src  = (const int*)d_in[6];
    const int*   dst  = (const int*)d_in[7];
    const int*   rel  = (const int*)d_in[8];
    float* out = (float*)d_out;

    // one-time side stream + fork/join events (created on the first,
    // uncaptured, correctness call; reused by every capture/replay)
    static cudaStream_t s2 = nullptr;
    static cudaEvent_t evFork = nullptr, evJoin = nullptr;
    static bool streams_ok = false;
    if (!evJoin) {
        streams_ok =
            cudaStreamCreateWithFlags(&s2, cudaStreamNonBlocking) == cudaSuccess &&
            cudaEventCreateWithFlags(&evFork, cudaEventDisableTiming) == cudaSuccess &&
            cudaEventCreateWithFlags(&evJoin, cudaEventDisableTiming) == cudaSuccess;
    }

    void* counts_ptr = nullptr;
    cudaGetSymbolAddress(&counts_ptr, g_counts);

    cudaStream_t sb = streams_ok ? s2 : (cudaStream_t)0;   // CSR-build stream

    if (streams_ok) {
        cudaEventRecord(evFork, 0);
        cudaStreamWaitEvent(sb, evFork, 0);
    }

    // ---- CSR build (side stream; independent of transform) ----
    cudaMemsetAsync(counts_ptr, 0, N_NODES * sizeof(int), sb);
    hist_kernel<<<(N_EDGES + 255) / 256, 256, 0, sb>>>(dst);
    scan1_kernel<<<SB, SCB, 0, sb>>>();
    scan2_kernel<<<1, 32, 0, sb>>>();
    scan3_kernel<<<SB, SCB, 0, sb>>>();
    scatter_kernel<<<(N_EDGES + 255) / 256, 256, 0, sb>>>(src, dst, rel, norm);

    // ---- per-(node,rel) transform (main stream, runs concurrently) ----
    dim3 g1((N_NODES + NT - 1) / NT, NREL);
    transform_kernel<<<g1, TPB1>>>(x, W1, W2, b1);

    if (streams_ok) {
        cudaEventRecord(evJoin, sb);
        cudaStreamWaitEvent((cudaStream_t)0, evJoin, 0);
    }

    // ---- gather + reduce + bias + relu (needs both) ----
    agg_kernel<<<(N_NODES + GPD - 1) / GPD, TPBA>>>(b2, out);
}

// round 7
// speedup vs baseline: 1.8964x; 1.6761x over previous
#include <cuda_runtime.h>
#include <cuda_fp16.h>
#include <cstdint>

#define N_NODES 50000
#define N_EDGES 1600000
#define F 48
#define NREL 8

// transform tiling (tensor-core version)
#define NT 128          // nodes per block
#define TPB1 256        // 8 warps x 16 rows
#define SXP 56          // sX/sH row stride (halfs): 112B rows, conflict-free ldmatrix
#define SWP 56          // sW row stride (halfs)

// scan config
#define SCB 1024
#define SB ((N_NODES + SCB - 1) / SCB)   // 49 blocks

// agg config
#define GPD 16                            // dst nodes per block (16*12 = 192 thr)
#define TPBA 192

typedef unsigned long long u64;

// ------------------------- static device scratch ---------------------------
// h2 stored as fp16: 50000*8*48*2B = 38.4 MB -> L2-resident
__device__ __align__(16) __half g_h2h[(size_t)N_NODES * NREL * F];
__device__ int   g_counts[N_NODES];
__device__ int   g_offsets[N_NODES + 1];
__device__ int   g_cursors[N_NODES];
__device__ u64   g_recs[N_EDGES];                    // {norm:f32 hi, srel:u32 lo}
__device__ int   g_blocksums[SB];

// ------------------------------ PTX helpers --------------------------------
__device__ __forceinline__ uint32_t smem_u32(const void* p) {
    uint32_t a;
    asm("{ .reg .u64 t; cvta.to.shared.u64 t, %1; cvt.u32.u64 %0, t; }"
        : "=r"(a) : "l"(p));
    return a;
}
__device__ __forceinline__ void ldm_x4(uint32_t& r0, uint32_t& r1,
                                       uint32_t& r2, uint32_t& r3, uint32_t addr) {
    asm volatile("ldmatrix.sync.aligned.m8n8.x4.shared.b16 {%0,%1,%2,%3}, [%4];"
                 : "=r"(r0), "=r"(r1), "=r"(r2), "=r"(r3) : "r"(addr));
}
__device__ __forceinline__ void ldm_x2_trans(uint32_t& r0, uint32_t& r1, uint32_t addr) {
    asm volatile("ldmatrix.sync.aligned.m8n8.x2.trans.shared.b16 {%0,%1}, [%2];"
                 : "=r"(r0), "=r"(r1) : "r"(addr));
}
__device__ __forceinline__ void mma16816(float* c, const uint32_t* a, const uint32_t* b) {
    asm volatile(
        "mma.sync.aligned.m16n8k16.row.col.f32.f16.f16.f32 "
        "{%0,%1,%2,%3},{%4,%5,%6,%7},{%8,%9},{%0,%1,%2,%3};"
        : "+f"(c[0]), "+f"(c[1]), "+f"(c[2]), "+f"(c[3])
        : "r"(a[0]), "r"(a[1]), "r"(a[2]), "r"(a[3]), "r"(b[0]), "r"(b[1]));
}

// ---------------------------------------------------------------------------
// Kernel 1 (HMMA): h2[n,r,:] = relu(x[n] @ W1[r] + b1) @ W2[r], stored fp16
// Block = 128 nodes x 1 rel, 8 warps, warp owns 16 rows. Per phase, per warp:
// A = ldmatrix.x4 (3 k-frags preloaded), B = ldmatrix.x2.trans of W[k][n],
// 6 n-tiles x 3 k-steps of mma.m16n8k16. Phase1->phase2 handoff is warp-local
// (same 16 rows), so only __syncwarp between phases.
// ---------------------------------------------------------------------------
__global__ __launch_bounds__(TPB1) void transform_kernel(
    const float* __restrict__ x, const float* __restrict__ W1,
    const float* __restrict__ W2, const float* __restrict__ b1)
{
    __shared__ __align__(16) __half sX[NT][SXP];   // x fp16, reused as h1 fp16
    __shared__ __align__(16) __half sW1h[F][SWP];
    __shared__ __align__(16) __half sW2h[F][SWP];

    const int r    = blockIdx.y;
    const int n0b  = blockIdx.x * NT;
    const int tid  = threadIdx.x;
    const int warp = tid >> 5;
    const int lane = tid & 31;

    // ---- stage weights (fp32 -> fp16) ----
    const size_t wbase = (size_t)r * F * F;
    for (int idx = tid; idx < F * F; idx += TPB1) {
        sW1h[idx / F][idx % F] = __float2half(W1[wbase + idx]);
        sW2h[idx / F][idx % F] = __float2half(W2[wbase + idx]);
    }
    // ---- stage x (fp32 -> fp16), vectorized, zero-pad OOB rows ----
    for (int idx = tid; idx < NT * F / 4; idx += TPB1) {
        int row = idx / (F / 4);
        int c4  = (idx % (F / 4)) * 4;
        int gn  = n0b + row;
        float4 v = (gn < N_NODES)
            ? *reinterpret_cast<const float4*>(&x[(size_t)gn * F + c4])
            : make_float4(0.f, 0.f, 0.f, 0.f);
        *reinterpret_cast<__half2*>(&sX[row][c4])     = __floats2half2_rn(v.x, v.y);
        *reinterpret_cast<__half2*>(&sX[row][c4 + 2]) = __floats2half2_rn(v.z, v.w);
    }
    __syncthreads();

    const uint32_t sx_base  = smem_u32(&sX[0][0]);
    const uint32_t sw1_base = smem_u32(&sW1h[0][0]);
    const uint32_t sw2_base = smem_u32(&sW2h[0][0]);

    const int arow = warp * 16 + (lane & 15);         // ldmatrix A row
    const int acol = (lane >> 4) * 8;                 // 0 or 8
    const int g4   = lane >> 2;                       // C row within 8
    const int t4   = lane & 3;                        // C col pair

    uint32_t a[3][4];
    float    c[6][4];

    // =================== phase 1: h1 = relu(x @ W1 + b1) ===================
    #pragma unroll
    for (int kk = 0; kk < 3; kk++) {
        uint32_t addr = sx_base + (uint32_t)((arow * SXP + acol + kk * 16) * 2);
        ldm_x4(a[kk][0], a[kk][1], a[kk][2], a[kk][3], addr);
    }
    #pragma unroll
    for (int t = 0; t < 6; t++)
        #pragma unroll
        for (int i = 0; i < 4; i++) c[t][i] = 0.f;

    #pragma unroll
    for (int t = 0; t < 6; t++) {
        const int n0 = t * 8;
        #pragma unroll
        for (int kk = 0; kk < 3; kk++) {
            uint32_t b[2];
            uint32_t addr = sw1_base + (uint32_t)(((kk * 16 + (lane & 15)) * SWP + n0) * 2);
            ldm_x2_trans(b[0], b[1], addr);
            mma16816(c[t], a[kk], b);
        }
    }

    // epilogue 1: bias + relu, pack fp16 back into sX (same rows this warp owns)
    {
        const int row0 = warp * 16 + g4;
        #pragma unroll
        for (int t = 0; t < 6; t++) {
            const int col = t * 8 + 2 * t4;
            float bx = __ldg(&b1[col]);
            float by = __ldg(&b1[col + 1]);
            *reinterpret_cast<__half2*>(&sX[row0][col]) =
                __floats2half2_rn(fmaxf(c[t][0] + bx, 0.f), fmaxf(c[t][1] + by, 0.f));
            *reinterpret_cast<__half2*>(&sX[row0 + 8][col]) =
                __floats2half2_rn(fmaxf(c[t][2] + bx, 0.f), fmaxf(c[t][3] + by, 0.f));
        }
    }
    __syncwarp();   // warp-local handoff: stores above -> ldmatrix below

    // =================== phase 2: h2 = h1 @ W2 ===================
    #pragma unroll
    for (int kk = 0; kk < 3; kk++) {
        uint32_t addr = sx_base + (uint32_t)((arow * SXP + acol + kk * 16) * 2);
        ldm_x4(a[kk][0], a[kk][1], a[kk][2], a[kk][3], addr);
    }
    #pragma unroll
    for (int t = 0; t < 6; t++)
        #pragma unroll
        for (int i = 0; i < 4; i++) c[t][i] = 0.f;

    #pragma unroll
    for (int t = 0; t < 6; t++) {
        const int n0 = t * 8;
        #pragma unroll
        for (int kk = 0; kk < 3; kk++) {
            uint32_t b[2];
            uint32_t addr = sw2_base + (uint32_t)(((kk * 16 + (lane & 15)) * SWP + n0) * 2);
            ldm_x2_trans(b[0], b[1], addr);
            mma16816(c[t], a[kk], b);
        }
    }

    // epilogue 2: store h2 fp16
    {
        const int gn0 = n0b + warp * 16 + g4;
        const int gn1 = gn0 + 8;
        #pragma unroll
        for (int t = 0; t < 6; t++) {
            const int col = t * 8 + 2 * t4;
            if (gn0 < N_NODES)
                *reinterpret_cast<__half2*>(
                    &g_h2h[((size_t)gn0 * NREL + r) * F + col]) =
                    __floats2half2_rn(c[t][0], c[t][1]);
            if (gn1 < N_NODES)
                *reinterpret_cast<__half2*>(
                    &g_h2h[((size_t)gn1 * NREL + r) * F + col]) =
                    __floats2half2_rn(c[t][2], c[t][3]);
        }
    }
}

// ---------------------------------------------------------------------------
// CSR build: histogram -> scan -> scatter packed records
// ---------------------------------------------------------------------------
__global__ void hist_kernel(const int* __restrict__ dst)
{
    int e = blockIdx.x * blockDim.x + threadIdx.x;
    if (e < N_EDGES) atomicAdd(&g_counts[dst[e]], 1);
}

__global__ __launch_bounds__(SCB) void scan1_kernel()
{
    __shared__ int s[SCB];
    int tid = threadIdx.x;
    int i = blockIdx.x * SCB + tid;
    int v = (i < N_NODES) ? g_counts[i] : 0;
    s[tid] = v;
    __syncthreads();
    #pragma unroll
    for (int off = 1; off < SCB; off <<= 1) {
        int t = (tid >= off) ? s[tid - off] : 0;
        __syncthreads();
        s[tid] += t;
        __syncthreads();
    }
    if (i < N_NODES) g_offsets[i] = s[tid] - v;     // local exclusive
    if (tid == SCB - 1) g_blocksums[blockIdx.x] = s[tid];
}

__global__ void scan2_kernel()
{
    if (threadIdx.x == 0) {
        int run = 0;
        #pragma unroll
        for (int b = 0; b < SB; b++) {
            int t = g_blocksums[b];
            g_blocksums[b] = run;
            run += t;
        }
        g_offsets[N_NODES] = run;   // == N_EDGES
    }
}

__global__ __launch_bounds__(SCB) void scan3_kernel()
{
    int i = blockIdx.x * SCB + threadIdx.x;
    if (i < N_NODES) {
        int o = g_offsets[i] + g_blocksums[blockIdx.x];
        g_offsets[i] = o;
        g_cursors[i] = o;
    }
}

__global__ void scatter_kernel(
    const int* __restrict__ src, const int* __restrict__ dst,
    const int* __restrict__ rel, const float* __restrict__ norm)
{
    int e = blockIdx.x * blockDim.x + threadIdx.x;
    if (e >= N_EDGES) return;
    int d = dst[e];
    int pos = atomicAdd(&g_cursors[d], 1);
    uint32_t srel = (uint32_t)src[e] * NREL + (uint32_t)rel[e];
    uint32_t wb = __float_as_uint(norm[e]);
    g_recs[pos] = ((u64)wb << 32) | (u64)srel;
}

// ---------------------------------------------------------------------------
// Aggregation: 12 lanes per dst node; fp16 gather (8B per lane per edge),
// 4-edge unroll with 4 independent accumulators, fused bias2+relu store.
// ---------------------------------------------------------------------------
__device__ __forceinline__ void acc_edge(float4& a, u64 rec, int k)
{
    float w = __uint_as_float((uint32_t)(rec >> 32));
    uint2 p = *reinterpret_cast<const uint2*>(
        &g_h2h[(size_t)(uint32_t)rec * F + k * 4]);
    __half2 ha = *reinterpret_cast<__half2*>(&p.x);
    __half2 hb = *reinterpret_cast<__half2*>(&p.y);
    float2 fa = __half22float2(ha);
    float2 fb = __half22float2(hb);
    a.x += fa.x * w; a.y += fa.y * w;
    a.z += fb.x * w; a.w += fb.y * w;
}

__global__ __launch_bounds__(TPBA) void agg_kernel(
    const float* __restrict__ b2, float* __restrict__ out)
{
    const int tid = threadIdx.x;
    const int g = blockIdx.x * GPD + tid / 12;
    const int k = tid % 12;
    if (g >= N_NODES) return;

    const int start = g_offsets[g];
    const int end   = g_offsets[g + 1];

    float4 a0 = make_float4(0.f, 0.f, 0.f, 0.f);
    float4 a1 = make_float4(0.f, 0.f, 0.f, 0.f);
    float4 a2 = make_float4(0.f, 0.f, 0.f, 0.f);
    float4 a3 = make_float4(0.f, 0.f, 0.f, 0.f);

    int e = start;
    for (; e + 3 < end; e += 4) {
        u64 r0 = g_recs[e];
        u64 r1 = g_recs[e + 1];
        u64 r2 = g_recs[e + 2];
        u64 r3 = g_recs[e + 3];
        acc_edge(a0, r0, k);
        acc_edge(a1, r1, k);
        acc_edge(a2, r2, k);
        acc_edge(a3, r3, k);
    }
    for (; e < end; e++) acc_edge(a0, g_recs[e], k);

    float4 bv = reinterpret_cast<const float4*>(b2)[k];
    float4 o;
    o.x = fmaxf(a0.x + a1.x + a2.x + a3.x + bv.x, 0.f);
    o.y = fmaxf(a0.y + a1.y + a2.y + a3.y + bv.y, 0.f);
    o.z = fmaxf(a0.z + a1.z + a2.z + a3.z + bv.z, 0.f);
    o.w = fmaxf(a0.w + a1.w + a2.w + a3.w + bv.w, 0.f);
    *reinterpret_cast<float4*>(&out[(size_t)g * F + k * 4]) = o;
}

// ---------------------------------------------------------------------------
extern "C" void kernel_launch(void* const* d_in, const int* in_sizes, int n_in,
                              void* d_out, int out_size)
{
    const float* x    = (const float*)d_in[0];
    const float* norm = (const float*)d_in[1];
    const float* W1   = (const float*)d_in[2];
    const float* W2   = (const float*)d_in[3];
    const float* b1   = (const float*)d_in[4];
    const float* b2   = (const float*)d_in[5];
    const int*   src  = (const int*)d_in[6];
    const int*   dst  = (const int*)d_in[7];
    const int*   rel  = (const int*)d_in[8];
    float* out = (float*)d_out;

    // one-time side stream + fork/join events (created on the first,
    // uncaptured, correctness call; reused by every capture/replay)
    static cudaStream_t s2 = nullptr;
    static cudaEvent_t evFork = nullptr, evJoin = nullptr;
    static bool streams_ok = false;
    if (!evJoin) {
        streams_ok =
            cudaStreamCreateWithFlags(&s2, cudaStreamNonBlocking) == cudaSuccess &&
            cudaEventCreateWithFlags(&evFork, cudaEventDisableTiming) == cudaSuccess &&
            cudaEventCreateWithFlags(&evJoin, cudaEventDisableTiming) == cudaSuccess;
    }

    void* counts_ptr = nullptr;
    cudaGetSymbolAddress(&counts_ptr, g_counts);

    cudaStream_t sb = streams_ok ? s2 : (cudaStream_t)0;   // CSR-build stream

    if (streams_ok) {
        cudaEventRecord(evFork, 0);
        cudaStreamWaitEvent(sb, evFork, 0);
    }

    // ---- CSR build (side stream; independent of transform) ----
    cudaMemsetAsync(counts_ptr, 0, N_NODES * sizeof(int), sb);
    hist_kernel<<<(N_EDGES + 255) / 256, 256, 0, sb>>>(dst);
    scan1_kernel<<<SB, SCB, 0, sb>>>();
    scan2_kernel<<<1, 32, 0, sb>>>();
    scan3_kernel<<<SB, SCB, 0, sb>>>();
    scatter_kernel<<<(N_EDGES + 255) / 256, 256, 0, sb>>>(src, dst, rel, norm);

    // ---- per-(node,rel) transform (main stream, runs concurrently) ----
    dim3 g1((N_NODES + NT - 1) / NT, NREL);
    transform_kernel<<<g1, TPB1>>>(x, W1, W2, b1);

    if (streams_ok) {
        cudaEventRecord(evJoin, sb);
        cudaStreamWaitEvent((cudaStream_t)0, evJoin, 0);
    }

    // ---- gather + reduce + bias + relu (needs both) ----
    agg_kernel<<<(N_NODES + GPD - 1) / GPD, TPBA>>>(b2, out);
}